// round 16
// baseline (speedup 1.0000x reference)
#include <cuda_runtime.h>
#include <cuda_fp16.h>
#include <math.h>
#include <cstdint>

#define NPTS (1 << 20)
#define RES 128
#define LDW 264   // K-stride (halves): LDSM conflict-free (4-bank row rotation)
#define LDW0 56   // K-stride for the 48-wide layer-0 input (28-bank rotation)
#define LDH3Q 72  // h3 staging stride (halves) in quarter kernel

// Scratch activations (device globals: allocation-free per harness rules)
static __device__ __align__(16) __half g_h1[(size_t)NPTS * 256];
static __device__ __align__(16) __half g_h2[(size_t)NPTS * 256];
// Packed tri-plane features: [plane][pixel][rank], half8 = 16B per pixel
static __device__ __align__(16) __half g_fp[3 * RES * RES * 8];

__device__ __forceinline__ uint32_t smem_u32(const void* p) {
    uint32_t a;
    asm("{ .reg .u64 t; cvta.to.shared.u64 t, %1; cvt.u32.u64 %0, t; }" : "=r"(a) : "l"(p));
    return a;
}

__device__ __forceinline__ void mma16816(float c[4], const unsigned a[4], const unsigned b[2]) {
    asm volatile(
        "mma.sync.aligned.m16n8k16.row.col.f32.f16.f16.f32 "
        "{%0,%1,%2,%3},{%4,%5,%6,%7},{%8,%9},{%0,%1,%2,%3};\n"
        : "+f"(c[0]), "+f"(c[1]), "+f"(c[2]), "+f"(c[3])
        : "r"(a[0]), "r"(a[1]), "r"(a[2]), "r"(a[3]), "r"(b[0]), "r"(b[1]));
}

__device__ __forceinline__ void ldsm4(unsigned& r0, unsigned& r1, unsigned& r2, unsigned& r3,
                                      uint32_t addr) {
    asm volatile("ldmatrix.sync.aligned.m8n8.x4.shared.b16 {%0,%1,%2,%3}, [%4];"
                 : "=r"(r0), "=r"(r1), "=r"(r2), "=r"(r3) : "r"(addr));
}

// 16m x 128n x KDIM warp GEMM (layer-0 kernel only)
template <int KDIM, int LDA, int LDB>
__device__ __forceinline__ void gemm_ldsm(uint32_t aA, uint32_t aB,
                                          int m0, int n0, int lane, float acc[16][4]) {
    const int q = lane >> 3, t7 = lane & 7;
    uint32_t a_addr = aA + (uint32_t)(((m0 + (q & 1) * 8 + t7) * LDA + (q >> 1) * 8) * 2);
    uint32_t b_base = aB + (uint32_t)(((n0 + (q >> 1) * 8 + t7) * LDB + (q & 1) * 8) * 2);
#pragma unroll
    for (int k0 = 0; k0 < KDIM; k0 += 16) {
        unsigned a[4];
        ldsm4(a[0], a[1], a[2], a[3], a_addr);
        a_addr += 32;
        uint32_t b_addr = b_base;
#pragma unroll
        for (int nt = 0; nt < 16; nt += 2) {
            unsigned b[4];
            ldsm4(b[0], b[1], b[2], b[3], b_addr);
            b_addr += 16 * LDB * 2;
            mma16816(acc[nt],     a, &b[0]);
            mma16816(acc[nt + 1], a, &b[2]);
        }
        b_base += 32;
    }
}

extern __shared__ char smem_raw[];

// ============================================================================
// k_pack: transpose tri-planes fp32[8][128][128] -> half[pixel][8] (16B/pixel)
// ============================================================================
__global__ void k_pack(const float* __restrict__ fxy, const float* __restrict__ fxz,
                       const float* __restrict__ fyz, __half* __restrict__ fp) {
    int i = blockIdx.x * blockDim.x + threadIdx.x;
    if (i >= 3 * RES * RES) return;
    int plane = i / (RES * RES), pix = i % (RES * RES);
    const float* src = (plane == 0) ? fxy : (plane == 1) ? fxz : fyz;
    __half tmp[8];
#pragma unroll
    for (int r = 0; r < 8; r++)
        tmp[r] = __float2half(src[r * (RES * RES) + pix]);
    *(uint4*)&fp[((size_t)plane * (RES * RES) + pix) * 8] = *(const uint4*)tmp;
}

// ============================================================================
// K0: encode (packed-feature gather + PE via double-angle recurrence) + layer0
// 256 threads, M-tile 64. 2 CTAs/SM to hide gather latency.
// ============================================================================
__global__ void __launch_bounds__(256, 2) k_enc0(
    const float* __restrict__ x,
    const __half* __restrict__ fp,
    const float* __restrict__ W0, const float* __restrict__ b0,
    __half* __restrict__ h_out) {
    __half* Wt0 = (__half*)smem_raw;
    float*  b0s = (float*)(Wt0 + 256 * LDW0);
    __half* A0  = (__half*)(b0s + 256);

    const int tid = threadIdx.x;

    for (int i = tid; i < 48 * 256; i += 256) {
        int k = i >> 8, n = i & 255;
        Wt0[n * LDW0 + k] = __float2half(k < 47 ? W0[k * 256 + n] : 0.f);
    }
    if (tid < 256) b0s[tid] = b0[tid];
    __syncthreads();

    const uint32_t aA0 = smem_u32(A0), aW0 = smem_u32(Wt0);
    const int wid = tid >> 5, lane = tid & 31;
    const int m0 = (wid >> 1) * 16, n0 = (wid & 1) * 128;
    const int g = lane >> 2, r = lane & 3;
    const int p = tid >> 2, c = tid & 3;   // 4 threads per point

    const uint4* p_xy = (const uint4*)fp;
    const uint4* p_xz = (const uint4*)(fp + (size_t)(RES * RES) * 8);
    const uint4* p_yz = (const uint4*)(fp + (size_t)2 * (RES * RES) * 8);

    for (int tile = blockIdx.x; tile < NPTS / 64; tile += gridDim.x) {
        {
            size_t pg = (size_t)tile * 64 + p;
            float xv = x[pg * 3 + 0], yv = x[pg * 3 + 1], zv = x[pg * 3 + 2];
            __half* arow = A0 + p * LDW0;
            if (c == 0) {
                int ix = min(max((int)((xv + 1.f) * 0.5f * (RES - 1)), 0), RES - 1);
                int iy = min(max((int)((yv + 1.f) * 0.5f * (RES - 1)), 0), RES - 1);
                int iz = min(max((int)((zv + 1.f) * 0.5f * (RES - 1)), 0), RES - 1);
                uint4 va = p_xy[iy * RES + ix];
                uint4 vb = p_xz[iz * RES + ix];
                uint4 vc = p_yz[iz * RES + iy];
                const __half2* ha = (const __half2*)&va;
                const __half2* hb = (const __half2*)&vb;
                const __half2* hc = (const __half2*)&vc;
                __half2* a2 = (__half2*)arow;
#pragma unroll
                for (int i2 = 0; i2 < 4; i2++)
                    a2[i2] = __hadd2(__hadd2(ha[i2], hb[i2]), hc[i2]);
                arow[8]  = __float2half(xv);
                arow[9]  = __float2half(yv);
                arow[10] = __float2half(zv);
                arow[47] = __float2half(0.f);
            } else {
                int c1 = c - 1;
                float cv = (c1 == 0) ? xv : (c1 == 1) ? yv : zv;
                float s, co;
                __sincosf(cv, &s, &co);
#pragma unroll
                for (int l = 0; l < 6; l++) {
                    arow[11 + l * 6 + c1]     = __float2half(s);
                    arow[11 + l * 6 + 3 + c1] = __float2half(co);
                    float s2 = 2.f * s * co;
                    float c2 = fmaf(2.f * co, co, -1.f);
                    s = s2; co = c2;
                }
            }
        }
        __syncthreads();

        float acc[16][4];
#pragma unroll
        for (int t = 0; t < 16; t++) acc[t][0] = acc[t][1] = acc[t][2] = acc[t][3] = 0.f;
        gemm_ldsm<48, LDW0, LDW0>(aA0, aW0, m0, n0, lane, acc);

        __half* outp = h_out + (size_t)tile * 64 * 256;
#pragma unroll
        for (int t = 0; t < 16; t++) {
            int nc = n0 + t * 8 + r * 2;
            float bb0 = b0s[nc], bb1 = b0s[nc + 1];
            float f0 = fmaxf(acc[t][0] + bb0, 0.f), f1 = fmaxf(acc[t][1] + bb1, 0.f);
            float f2 = fmaxf(acc[t][2] + bb0, 0.f), f3 = fmaxf(acc[t][3] + bb1, 0.f);
            *(__half2*)&outp[(size_t)(m0 + g) * 256 + nc]     = __floats2half2_rn(f0, f1);
            *(__half2*)&outp[(size_t)(m0 + g + 8) * 256 + nc] = __floats2half2_rn(f2, f3);
        }
        __syncthreads();
    }
}

// ============================================================================
// Quarter-split register-B hidden layer. 256 thr, 8 warps (2m x 4n of
// 32m x 16n tiles). CTA tile 64m x 64n; n-quarter = blockIdx.x & 3.
// Br = 64 regs -> ~100 regs/thread -> 2 CTAs/SM (4 warps/SMSP).
// A tiles (64x256) cp.async double-buffered; B traffic zero in mainloop.
// HEADS: h3 quarter staged into A[buf]; 4-quarter partial dots -> part buffer.
// SMEM: A0 33792 | A1 33792 | bs 256 | Whh 512  = 68352 B  (<113KB for 2/SM)
// ============================================================================
#define SMQ_A1  33792
#define SMQ_BS  (2 * 33792)
#define SMQ_WH  (SMQ_BS + 256)
#define SMQ_TOT (SMQ_WH + 512)

__device__ __forceinline__ void prefetch_A64(uint32_t aDst, const __half* in, int tile, int tid) {
    const uint4* src = (const uint4*)(in + (size_t)tile * 64 * 256);
#pragma unroll
    for (int i = 0; i < 8; i++) {
        int v = tid + i * 256;
        int m = v >> 5, k = (v & 31) << 3;
        uint32_t dst = aDst + (uint32_t)((m * LDW + k) * 2);
        asm volatile("cp.async.cg.shared.global [%0], [%1], 16;"
                     :: "r"(dst), "l"(src + v) : "memory");
    }
}

template <bool HEADS>
__global__ void __launch_bounds__(256, 2) k_q(
    const float* __restrict__ W, const float* __restrict__ b,
    const float* __restrict__ Wsig, const float* __restrict__ Wrgb,
    const __half* __restrict__ in, void* __restrict__ outp) {
    __half*  A0  = (__half*)smem_raw;
    __half*  A1  = (__half*)(smem_raw + SMQ_A1);
    float*   bs  = (float*)(smem_raw + SMQ_BS);
    __half2* Whh = (__half2*)(smem_raw + SMQ_WH);  // [k2*4 + j], 128 entries

    const int tid = threadIdx.x;
    const int nq = blockIdx.x & 3;
    const int nbase = nq * 64;

    // ---- one-time: stage this CTA's W quarter (transposed fp16) into A0 ----
    __half* Wt = A0;
    for (int i = tid; i < 64 * 256; i += 256) {
        int k = i >> 6, nl = i & 63;
        Wt[nl * LDW + k] = __float2half(W[k * 256 + nbase + nl]);
    }
    if (tid < 64) bs[tid] = b[nbase + tid];
    if (HEADS && tid < 128) {
        int k2 = tid >> 2, j = tid & 3;   // k2 in 0..31
        int gk = nbase + 2 * k2;
        float w0 = (j < 3) ? Wrgb[gk * 3 + j] : Wsig[gk];
        float w1 = (j < 3) ? Wrgb[(gk + 1) * 3 + j] : Wsig[gk + 1];
        Whh[k2 * 4 + j] = __floats2half2_rn(w0, w1);
    }
    __syncthreads();

    // ---- extract B fragments into registers (once): warp covers 16n x 256k ----
    const int wid = tid >> 5, lane = tid & 31;
    const int q = lane >> 3, t7 = lane & 7;
    const int m0w = (wid & 1) * 32, n0w = (wid >> 1) * 16;
    unsigned Br[16][2][2];
    {
        const uint32_t aW = smem_u32(Wt);
        uint32_t brow = aW + (uint32_t)(((n0w + (q >> 1) * 8 + t7) * LDW + (q & 1) * 8) * 2);
#pragma unroll
        for (int k = 0; k < 16; k++)
            ldsm4(Br[k][0][0], Br[k][0][1], Br[k][1][0], Br[k][1][1], brow + k * 32);
    }
    __syncthreads();  // all warps done with Wt; A0 region reusable

    const uint32_t aAb[2] = { smem_u32(A0), smem_u32(A1) };
    __half* Abuf[2] = { A0, A1 };
    const int g = lane >> 2, r = lane & 3;
    const int tstride = gridDim.x >> 2;
    const int NT = NPTS / 64;

    prefetch_A64(aAb[0], in, blockIdx.x >> 2, tid);
    asm volatile("cp.async.commit_group;" ::: "memory");

    int buf = 0;
    for (int t = blockIdx.x >> 2; t < NT; t += tstride, buf ^= 1) {
        asm volatile("cp.async.wait_group 0;" ::: "memory");
        __syncthreads();
        int tn = t + tstride;
        if (tn < NT) prefetch_A64(aAb[buf ^ 1], in, tn, tid);
        asm volatile("cp.async.commit_group;" ::: "memory");

        float acc[2][2][4];
#pragma unroll
        for (int mf = 0; mf < 2; mf++)
#pragma unroll
            for (int nf = 0; nf < 2; nf++)
                acc[mf][nf][0] = acc[mf][nf][1] = acc[mf][nf][2] = acc[mf][nf][3] = 0.f;

        uint32_t a_base = aAb[buf] + (uint32_t)(((m0w + (q & 1) * 8 + t7) * LDW + (q >> 1) * 8) * 2);
#pragma unroll
        for (int k = 0; k < 16; k++) {
            unsigned a[2][4];
#pragma unroll
            for (int mf = 0; mf < 2; mf++)
                ldsm4(a[mf][0], a[mf][1], a[mf][2], a[mf][3],
                      a_base + (uint32_t)(mf * 16 * LDW * 2) + k * 32);
#pragma unroll
            for (int nf = 0; nf < 2; nf++)
#pragma unroll
                for (int mf = 0; mf < 2; mf++)
                    mma16816(acc[mf][nf], a[mf], Br[k][nf]);
        }

        if (!HEADS) {
            __half* orow = (__half*)outp + (size_t)t * 64 * 256;
#pragma unroll
            for (int mf = 0; mf < 2; mf++) {
                int mr = m0w + mf * 16;
#pragma unroll
                for (int nf = 0; nf < 2; nf++) {
                    int nl = n0w + nf * 8 + r * 2;
                    int nc = nbase + nl;
                    float bb0 = bs[nl], bb1 = bs[nl + 1];
                    float f0 = fmaxf(acc[mf][nf][0] + bb0, 0.f), f1 = fmaxf(acc[mf][nf][1] + bb1, 0.f);
                    float f2 = fmaxf(acc[mf][nf][2] + bb0, 0.f), f3 = fmaxf(acc[mf][nf][3] + bb1, 0.f);
                    *(__half2*)&orow[(size_t)(mr + g) * 256 + nc]     = __floats2half2_rn(f0, f1);
                    *(__half2*)&orow[(size_t)(mr + g + 8) * 256 + nc] = __floats2half2_rn(f2, f3);
                }
            }
        } else {
            // h3 quarter (64m x 64n local) -> stage into A[buf] at stride LDH3Q
            __syncthreads();
            __half* H3 = Abuf[buf];
#pragma unroll
            for (int mf = 0; mf < 2; mf++) {
                int mr = m0w + mf * 16;
#pragma unroll
                for (int nf = 0; nf < 2; nf++) {
                    int nl = n0w + nf * 8 + r * 2;
                    float bb0 = bs[nl], bb1 = bs[nl + 1];
                    float f0 = fmaxf(acc[mf][nf][0] + bb0, 0.f), f1 = fmaxf(acc[mf][nf][1] + bb1, 0.f);
                    float f2 = fmaxf(acc[mf][nf][2] + bb0, 0.f), f3 = fmaxf(acc[mf][nf][3] + bb1, 0.f);
                    *(__half2*)&H3[(mr + g) * LDH3Q + nl]     = __floats2half2_rn(f0, f1);
                    *(__half2*)&H3[(mr + g + 8) * LDH3Q + nl] = __floats2half2_rn(f2, f3);
                }
            }
            __syncthreads();

            // partial head dots over this CTA's 64 features; 1 point per 4 threads
            const int pj = tid & 3, p = tid >> 2;
            const uint4* hr4 = (const uint4*)(H3 + p * LDH3Q);  // 8 x (8 halves)
            float v = 0.f;
#pragma unroll
            for (int k4 = 0; k4 < 8; k4++) {
                uint4 hv = hr4[k4];
                const __half2* hp = (const __half2*)&hv;
#pragma unroll
                for (int i = 0; i < 4; i++) {
                    float2 h = __half22float2(hp[i]);
                    float2 w = __half22float2(Whh[(k4 * 4 + i) * 4 + pj]);
                    v += h.x * w.x + h.y * w.y;
                }
            }
            float* part = (float*)outp;
            part[(size_t)(nq * 4 + pj) * NPTS + (size_t)t * 64 + p] = v;
            __syncthreads();  // head reads of A[buf] done before its next fill
        }
    }
}

// ============================================================================
// Final: combine 4 quarter partials, apply bias + sigmoid / softplus.
// ============================================================================
__global__ void k_final(const float* __restrict__ part,
                        const float* __restrict__ bsig, const float* __restrict__ brgb,
                        float* __restrict__ out) {
    int i = blockIdx.x * blockDim.x + threadIdx.x;
    if (i >= 4 * NPTS) return;
    int j = i >> 20;
    int p = i & (NPTS - 1);
    float v = part[(size_t)j * NPTS + p] + part[(size_t)(4 + j) * NPTS + p]
            + part[(size_t)(8 + j) * NPTS + p] + part[(size_t)(12 + j) * NPTS + p];
    if (j < 3) {
        v += brgb[j];
        out[(size_t)p * 3 + j] = 1.f / (1.f + expf(-v));
    } else {
        v += bsig[0];
        out[(size_t)3 * NPTS + p] = (v > 20.f) ? v : log1pf(expf(v));
    }
}

// ============================================================================
extern "C" void kernel_launch(void* const* d_in, const int* in_sizes, int n_in,
                              void* d_out, int out_size) {
    const float* x    = (const float*)d_in[0];
    const float* fxy  = (const float*)d_in[1];
    const float* fxz  = (const float*)d_in[2];
    const float* fyz  = (const float*)d_in[3];
    const float* W0   = (const float*)d_in[4];
    const float* b0   = (const float*)d_in[5];
    const float* W1   = (const float*)d_in[6];
    const float* b1   = (const float*)d_in[7];
    const float* W2   = (const float*)d_in[8];
    const float* b2   = (const float*)d_in[9];
    const float* W3   = (const float*)d_in[10];
    const float* b3   = (const float*)d_in[11];
    const float* Wsig = (const float*)d_in[12];
    const float* bsig = (const float*)d_in[13];
    const float* Wrgb = (const float*)d_in[14];
    const float* brgb = (const float*)d_in[15];

    void *p1, *p2, *pf;
    cudaGetSymbolAddress(&p1, g_h1);
    cudaGetSymbolAddress(&p2, g_h2);
    cudaGetSymbolAddress(&pf, g_fp);

    int nsm = 148;
    cudaDeviceGetAttribute(&nsm, cudaDevAttrMultiProcessorCount, 0);
    int grid = (2 * nsm) & ~3;  // 2 CTAs/SM, multiple of 4 for quarter split

    const size_t S0 = 256 * LDW0 * 2 + 256 * 4 + 64 * LDW0 * 2;

    cudaFuncSetAttribute(k_enc0,     cudaFuncAttributeMaxDynamicSharedMemorySize, (int)S0);
    cudaFuncSetAttribute(k_q<false>, cudaFuncAttributeMaxDynamicSharedMemorySize, SMQ_TOT);
    cudaFuncSetAttribute(k_q<true>,  cudaFuncAttributeMaxDynamicSharedMemorySize, SMQ_TOT);

    // pack tri-planes -> g_fp (pixel-major half8)
    k_pack<<<(3 * RES * RES + 255) / 256, 256>>>(fxy, fxz, fyz, (__half*)pf);
    // encode + L0 -> h1 (p1); 2 CTAs/SM
    k_enc0<<<2 * nsm, 256, S0>>>(x, (const __half*)pf, W0, b0, (__half*)p1);
    // L1: p1 -> p2
    k_q<false><<<grid, 256, SMQ_TOT>>>(W1, b1, nullptr, nullptr,
                                       (const __half*)p1, p2);
    // L2: p2 -> p1
    k_q<false><<<grid, 256, SMQ_TOT>>>(W2, b2, nullptr, nullptr,
                                       (const __half*)p2, p1);
    // L3 + partial heads: p1 -> partial sums in p2 (reused as float scratch)
    k_q<true><<<grid, 256, SMQ_TOT>>>(W3, b3, Wsig, Wrgb,
                                      (const __half*)p1, p2);
    // combine partials -> out
    k_final<<<(4 * NPTS + 255) / 256, 256>>>((const float*)p2, bsig, brgb, (float*)d_out);
}

// round 17
// speedup vs baseline: 1.1097x; 1.1097x over previous
#include <cuda_runtime.h>
#include <cuda_fp16.h>
#include <math.h>
#include <cstdint>

#define NPTS (1 << 20)
#define RES 128
#define LDW 264   // K-stride (halves): LDSM conflict-free (4-bank row rotation)
#define LDW0 56   // K-stride for the 48-wide layer-0 input (28-bank rotation)
#define LDH3 136  // h3 staging stride (halves), 16B-aligned rows

// Scratch activations (device globals: allocation-free per harness rules)
static __device__ __align__(16) __half g_h1[(size_t)NPTS * 256];
static __device__ __align__(16) __half g_h2[(size_t)NPTS * 256];
// Packed tri-plane features: [plane][pixel][rank], half8 = 16B per pixel
static __device__ __align__(16) __half g_fp[3 * RES * RES * 8];

__device__ __forceinline__ uint32_t smem_u32(const void* p) {
    uint32_t a;
    asm("{ .reg .u64 t; cvta.to.shared.u64 t, %1; cvt.u32.u64 %0, t; }" : "=r"(a) : "l"(p));
    return a;
}

__device__ __forceinline__ void mma16816(float c[4], const unsigned a[4], const unsigned b[2]) {
    asm volatile(
        "mma.sync.aligned.m16n8k16.row.col.f32.f16.f16.f32 "
        "{%0,%1,%2,%3},{%4,%5,%6,%7},{%8,%9},{%0,%1,%2,%3};\n"
        : "+f"(c[0]), "+f"(c[1]), "+f"(c[2]), "+f"(c[3])
        : "r"(a[0]), "r"(a[1]), "r"(a[2]), "r"(a[3]), "r"(b[0]), "r"(b[1]));
}

// fp16-accumulator variant: D/C are 2 regs = 4 halves (row g cols r*2..+1 | row g+8)
__device__ __forceinline__ void mma16816h(unsigned c[2], const unsigned a[4], const unsigned b[2]) {
    asm volatile(
        "mma.sync.aligned.m16n8k16.row.col.f16.f16.f16.f16 "
        "{%0,%1},{%2,%3,%4,%5},{%6,%7},{%0,%1};\n"
        : "+r"(c[0]), "+r"(c[1])
        : "r"(a[0]), "r"(a[1]), "r"(a[2]), "r"(a[3]), "r"(b[0]), "r"(b[1]));
}

__device__ __forceinline__ void ldsm4(unsigned& r0, unsigned& r1, unsigned& r2, unsigned& r3,
                                      uint32_t addr) {
    asm volatile("ldmatrix.sync.aligned.m8n8.x4.shared.b16 {%0,%1,%2,%3}, [%4];"
                 : "=r"(r0), "=r"(r1), "=r"(r2), "=r"(r3) : "r"(addr));
}

// 16m x 128n x KDIM warp GEMM (layer-0 kernel only)
template <int KDIM, int LDA, int LDB>
__device__ __forceinline__ void gemm_ldsm(uint32_t aA, uint32_t aB,
                                          int m0, int n0, int lane, float acc[16][4]) {
    const int q = lane >> 3, t7 = lane & 7;
    uint32_t a_addr = aA + (uint32_t)(((m0 + (q & 1) * 8 + t7) * LDA + (q >> 1) * 8) * 2);
    uint32_t b_base = aB + (uint32_t)(((n0 + (q >> 1) * 8 + t7) * LDB + (q & 1) * 8) * 2);
#pragma unroll
    for (int k0 = 0; k0 < KDIM; k0 += 16) {
        unsigned a[4];
        ldsm4(a[0], a[1], a[2], a[3], a_addr);
        a_addr += 32;
        uint32_t b_addr = b_base;
#pragma unroll
        for (int nt = 0; nt < 16; nt += 2) {
            unsigned b[4];
            ldsm4(b[0], b[1], b[2], b[3], b_addr);
            b_addr += 16 * LDB * 2;
            mma16816(acc[nt],     a, &b[0]);
            mma16816(acc[nt + 1], a, &b[2]);
        }
        b_base += 32;
    }
}

extern __shared__ char smem_raw[];

// ============================================================================
// k_pack: transpose tri-planes fp32[8][128][128] -> half[pixel][8] (16B/pixel)
// ============================================================================
__global__ void k_pack(const float* __restrict__ fxy, const float* __restrict__ fxz,
                       const float* __restrict__ fyz, __half* __restrict__ fp) {
    int i = blockIdx.x * blockDim.x + threadIdx.x;
    if (i >= 3 * RES * RES) return;
    int plane = i / (RES * RES), pix = i % (RES * RES);
    const float* src = (plane == 0) ? fxy : (plane == 1) ? fxz : fyz;
    __half tmp[8];
#pragma unroll
    for (int r = 0; r < 8; r++)
        tmp[r] = __float2half(src[r * (RES * RES) + pix]);
    *(uint4*)&fp[((size_t)plane * (RES * RES) + pix) * 8] = *(const uint4*)tmp;
}

// ============================================================================
// K0: encode (packed-feature gather + PE via double-angle recurrence) + layer0
// ============================================================================
__global__ void __launch_bounds__(256, 2) k_enc0(
    const float* __restrict__ x,
    const __half* __restrict__ fp,
    const float* __restrict__ W0, const float* __restrict__ b0,
    __half* __restrict__ h_out) {
    __half* Wt0 = (__half*)smem_raw;
    float*  b0s = (float*)(Wt0 + 256 * LDW0);
    __half* A0  = (__half*)(b0s + 256);

    const int tid = threadIdx.x;

    for (int i = tid; i < 48 * 256; i += 256) {
        int k = i >> 8, n = i & 255;
        Wt0[n * LDW0 + k] = __float2half(k < 47 ? W0[k * 256 + n] : 0.f);
    }
    if (tid < 256) b0s[tid] = b0[tid];
    __syncthreads();

    const uint32_t aA0 = smem_u32(A0), aW0 = smem_u32(Wt0);
    const int wid = tid >> 5, lane = tid & 31;
    const int m0 = (wid >> 1) * 16, n0 = (wid & 1) * 128;
    const int g = lane >> 2, r = lane & 3;
    const int p = tid >> 2, c = tid & 3;   // 4 threads per point

    const uint4* p_xy = (const uint4*)fp;
    const uint4* p_xz = (const uint4*)(fp + (size_t)(RES * RES) * 8);
    const uint4* p_yz = (const uint4*)(fp + (size_t)2 * (RES * RES) * 8);

    for (int tile = blockIdx.x; tile < NPTS / 64; tile += gridDim.x) {
        {
            size_t pg = (size_t)tile * 64 + p;
            float xv = x[pg * 3 + 0], yv = x[pg * 3 + 1], zv = x[pg * 3 + 2];
            __half* arow = A0 + p * LDW0;
            if (c == 0) {
                int ix = min(max((int)((xv + 1.f) * 0.5f * (RES - 1)), 0), RES - 1);
                int iy = min(max((int)((yv + 1.f) * 0.5f * (RES - 1)), 0), RES - 1);
                int iz = min(max((int)((zv + 1.f) * 0.5f * (RES - 1)), 0), RES - 1);
                uint4 va = p_xy[iy * RES + ix];
                uint4 vb = p_xz[iz * RES + ix];
                uint4 vc = p_yz[iz * RES + iy];
                const __half2* ha = (const __half2*)&va;
                const __half2* hb = (const __half2*)&vb;
                const __half2* hc = (const __half2*)&vc;
                __half2* a2 = (__half2*)arow;
#pragma unroll
                for (int i2 = 0; i2 < 4; i2++)
                    a2[i2] = __hadd2(__hadd2(ha[i2], hb[i2]), hc[i2]);
                arow[8]  = __float2half(xv);
                arow[9]  = __float2half(yv);
                arow[10] = __float2half(zv);
                arow[47] = __float2half(0.f);
            } else {
                int c1 = c - 1;
                float cv = (c1 == 0) ? xv : (c1 == 1) ? yv : zv;
                float s, co;
                __sincosf(cv, &s, &co);
#pragma unroll
                for (int l = 0; l < 6; l++) {
                    arow[11 + l * 6 + c1]     = __float2half(s);
                    arow[11 + l * 6 + 3 + c1] = __float2half(co);
                    float s2 = 2.f * s * co;
                    float c2 = fmaf(2.f * co, co, -1.f);
                    s = s2; co = c2;
                }
            }
        }
        __syncthreads();

        float acc[16][4];
#pragma unroll
        for (int t = 0; t < 16; t++) acc[t][0] = acc[t][1] = acc[t][2] = acc[t][3] = 0.f;
        gemm_ldsm<48, LDW0, LDW0>(aA0, aW0, m0, n0, lane, acc);

        __half* outp = h_out + (size_t)tile * 64 * 256;
#pragma unroll
        for (int t = 0; t < 16; t++) {
            int nc = n0 + t * 8 + r * 2;
            float bb0 = b0s[nc], bb1 = b0s[nc + 1];
            float f0 = fmaxf(acc[t][0] + bb0, 0.f), f1 = fmaxf(acc[t][1] + bb1, 0.f);
            float f2 = fmaxf(acc[t][2] + bb0, 0.f), f3 = fmaxf(acc[t][3] + bb1, 0.f);
            *(__half2*)&outp[(size_t)(m0 + g) * 256 + nc]     = __floats2half2_rn(f0, f1);
            *(__half2*)&outp[(size_t)(m0 + g + 8) * 256 + nc] = __floats2half2_rn(f2, f3);
        }
        __syncthreads();
    }
}

// ============================================================================
// Register-resident-B hidden layer, fp16 ACCUMULATOR (L1, L2). 256 thr,
// 8 warps (2m x 4n of 64m x 32n). CTA owns n-half; B frags in regs (128).
// acc is packed half2 matching output layout -> epilogue is hadd2+hmax2+STG.
// ============================================================================
#define SMR_A1  67584
#define SMR_BS  (2 * 67584)
#define SMR_H3  (SMR_BS + 512)
#define SMR_WH  (SMR_H3 + 128 * LDH3 * 2)
#define SMR_TOT_PLAIN (SMR_BS + 512)
#define SMR_TOT_HEADS (SMR_WH + 1024)

__device__ __forceinline__ void prefetch_A(uint32_t aDst, const __half* in, int tile, int tid) {
    const uint4* src = (const uint4*)(in + (size_t)tile * 128 * 256);
#pragma unroll
    for (int i = 0; i < 16; i++) {
        int v = tid + i * 256;
        int m = v >> 5, k = (v & 31) << 3;
        uint32_t dst = aDst + (uint32_t)((m * LDW + k) * 2);
        asm volatile("cp.async.cg.shared.global [%0], [%1], 16;"
                     :: "r"(dst), "l"(src + v) : "memory");
    }
}

__global__ void __launch_bounds__(256, 1) k_regB16(
    const float* __restrict__ W, const float* __restrict__ b,
    const __half* __restrict__ in, __half* __restrict__ outp) {
    __half*  A0  = (__half*)smem_raw;
    __half*  A1  = (__half*)(smem_raw + SMR_A1);
    __half2* bsh = (__half2*)(smem_raw + SMR_BS);   // 64 half2 = 128 cols

    const int tid = threadIdx.x;
    const int nh = blockIdx.x & 1;
    const int nbase = nh * 128;

    __half* Wt = A0;
    for (int i = tid; i < 128 * 256; i += 256) {
        int k = i >> 7, nl = i & 127;
        Wt[nl * LDW + k] = __float2half(W[k * 256 + nbase + nl]);
    }
    if (tid < 64)
        bsh[tid] = __floats2half2_rn(b[nbase + 2 * tid], b[nbase + 2 * tid + 1]);
    __syncthreads();

    const int wid = tid >> 5, lane = tid & 31;
    const int q = lane >> 3, t7 = lane & 7;
    const int m0w = (wid & 1) * 64, n0w = (wid >> 1) * 32;
    unsigned Br[16][4][2];
    {
        const uint32_t aW = smem_u32(Wt);
        uint32_t brow = aW + (uint32_t)(((n0w + (q >> 1) * 8 + t7) * LDW + (q & 1) * 8) * 2);
#pragma unroll
        for (int k = 0; k < 16; k++) {
#pragma unroll
            for (int np = 0; np < 2; np++) {
                ldsm4(Br[k][2 * np][0], Br[k][2 * np][1],
                      Br[k][2 * np + 1][0], Br[k][2 * np + 1][1],
                      brow + k * 32 + (uint32_t)(np * 16 * LDW * 2));
            }
        }
    }
    __syncthreads();

    const uint32_t aAb[2] = { smem_u32(A0), smem_u32(A1) };
    const int g = lane >> 2, r = lane & 3;
    const int tstride = gridDim.x >> 1;
    const int NT = NPTS / 128;

    prefetch_A(aAb[0], in, blockIdx.x >> 1, tid);
    asm volatile("cp.async.commit_group;" ::: "memory");

    int buf = 0;
    for (int t = blockIdx.x >> 1; t < NT; t += tstride, buf ^= 1) {
        asm volatile("cp.async.wait_group 0;" ::: "memory");
        __syncthreads();
        int tn = t + tstride;
        if (tn < NT) prefetch_A(aAb[buf ^ 1], in, tn, tid);
        asm volatile("cp.async.commit_group;" ::: "memory");

        unsigned acc[4][4][2];
#pragma unroll
        for (int mf = 0; mf < 4; mf++)
#pragma unroll
            for (int nf = 0; nf < 4; nf++)
                acc[mf][nf][0] = acc[mf][nf][1] = 0u;

        uint32_t a_base = aAb[buf] + (uint32_t)(((m0w + (q & 1) * 8 + t7) * LDW + (q >> 1) * 8) * 2);
#pragma unroll
        for (int k = 0; k < 16; k++) {
            unsigned a[4][4];
#pragma unroll
            for (int mf = 0; mf < 4; mf++)
                ldsm4(a[mf][0], a[mf][1], a[mf][2], a[mf][3],
                      a_base + (uint32_t)(mf * 16 * LDW * 2) + k * 32);
#pragma unroll
            for (int nf = 0; nf < 4; nf++)
#pragma unroll
                for (int mf = 0; mf < 4; mf++)
                    mma16816h(acc[mf][nf], a[mf], Br[k][nf]);
        }

        __half* orow = outp + (size_t)t * 128 * 256;
        const __half2 z2 = __floats2half2_rn(0.f, 0.f);
#pragma unroll
        for (int mf = 0; mf < 4; mf++) {
            int mr = m0w + mf * 16;
#pragma unroll
            for (int nf = 0; nf < 4; nf++) {
                int nl = n0w + nf * 8 + r * 2;
                int nc = nbase + nl;
                __half2 bb = bsh[nl >> 1];
                __half2 v0 = __hmax2(__hadd2(*(__half2*)&acc[mf][nf][0], bb), z2);
                __half2 v1 = __hmax2(__hadd2(*(__half2*)&acc[mf][nf][1], bb), z2);
                *(__half2*)&orow[(size_t)(mr + g) * 256 + nc]     = v0;
                *(__half2*)&orow[(size_t)(mr + g + 8) * 256 + nc] = v1;
            }
        }
    }
}

// ============================================================================
// Register-resident-B L3 + heads (fp32 accumulation, unchanged from R15).
// ============================================================================
__global__ void __launch_bounds__(256, 1) k_regB_heads(
    const float* __restrict__ W, const float* __restrict__ b,
    const float* __restrict__ Wsig, const float* __restrict__ Wrgb,
    const __half* __restrict__ in, void* __restrict__ outp) {
    __half*  A0  = (__half*)smem_raw;
    __half*  A1  = (__half*)(smem_raw + SMR_A1);
    float*   bs  = (float*)(smem_raw + SMR_BS);
    __half*  H3  = (__half*)(smem_raw + SMR_H3);
    __half2* Whh = (__half2*)(smem_raw + SMR_WH);  // [k2*4 + j], 256 entries

    const int tid = threadIdx.x;
    const int nh = blockIdx.x & 1;
    const int nbase = nh * 128;

    __half* Wt = A0;
    for (int i = tid; i < 128 * 256; i += 256) {
        int k = i >> 7, nl = i & 127;
        Wt[nl * LDW + k] = __float2half(W[k * 256 + nbase + nl]);
    }
    if (tid < 128) bs[tid] = b[nbase + tid];
    {
        int k2 = tid >> 2, j = tid & 3;
        int gk = nbase + 2 * k2;
        float w0 = (j < 3) ? Wrgb[gk * 3 + j] : Wsig[gk];
        float w1 = (j < 3) ? Wrgb[(gk + 1) * 3 + j] : Wsig[gk + 1];
        Whh[k2 * 4 + j] = __floats2half2_rn(w0, w1);
    }
    __syncthreads();

    const int wid = tid >> 5, lane = tid & 31;
    const int q = lane >> 3, t7 = lane & 7;
    const int m0w = (wid & 1) * 64, n0w = (wid >> 1) * 32;
    unsigned Br[16][4][2];
    {
        const uint32_t aW = smem_u32(Wt);
        uint32_t brow = aW + (uint32_t)(((n0w + (q >> 1) * 8 + t7) * LDW + (q & 1) * 8) * 2);
#pragma unroll
        for (int k = 0; k < 16; k++) {
#pragma unroll
            for (int np = 0; np < 2; np++) {
                ldsm4(Br[k][2 * np][0], Br[k][2 * np][1],
                      Br[k][2 * np + 1][0], Br[k][2 * np + 1][1],
                      brow + k * 32 + (uint32_t)(np * 16 * LDW * 2));
            }
        }
    }
    __syncthreads();

    const uint32_t aAb[2] = { smem_u32(A0), smem_u32(A1) };
    const int g = lane >> 2, r = lane & 3;
    const int tstride = gridDim.x >> 1;
    const int NT = NPTS / 128;

    prefetch_A(aAb[0], in, blockIdx.x >> 1, tid);
    asm volatile("cp.async.commit_group;" ::: "memory");

    int buf = 0;
    for (int t = blockIdx.x >> 1; t < NT; t += tstride, buf ^= 1) {
        asm volatile("cp.async.wait_group 0;" ::: "memory");
        __syncthreads();
        int tn = t + tstride;
        if (tn < NT) prefetch_A(aAb[buf ^ 1], in, tn, tid);
        asm volatile("cp.async.commit_group;" ::: "memory");

        float acc[4][4][4];
#pragma unroll
        for (int mf = 0; mf < 4; mf++)
#pragma unroll
            for (int nf = 0; nf < 4; nf++)
                acc[mf][nf][0] = acc[mf][nf][1] = acc[mf][nf][2] = acc[mf][nf][3] = 0.f;

        uint32_t a_base = aAb[buf] + (uint32_t)(((m0w + (q & 1) * 8 + t7) * LDW + (q >> 1) * 8) * 2);
#pragma unroll
        for (int k = 0; k < 16; k++) {
            unsigned a[4][4];
#pragma unroll
            for (int mf = 0; mf < 4; mf++)
                ldsm4(a[mf][0], a[mf][1], a[mf][2], a[mf][3],
                      a_base + (uint32_t)(mf * 16 * LDW * 2) + k * 32);
#pragma unroll
            for (int nf = 0; nf < 4; nf++)
#pragma unroll
                for (int mf = 0; mf < 4; mf++)
                    mma16816(acc[mf][nf], a[mf], Br[k][nf]);
        }

        // stage this CTA's h3 half (128m x 128cols local) into H3
#pragma unroll
        for (int mf = 0; mf < 4; mf++) {
            int mr = m0w + mf * 16;
#pragma unroll
            for (int nf = 0; nf < 4; nf++) {
                int nl = n0w + nf * 8 + r * 2;
                float bb0 = bs[nl], bb1 = bs[nl + 1];
                float f0 = fmaxf(acc[mf][nf][0] + bb0, 0.f), f1 = fmaxf(acc[mf][nf][1] + bb1, 0.f);
                float f2 = fmaxf(acc[mf][nf][2] + bb0, 0.f), f3 = fmaxf(acc[mf][nf][3] + bb1, 0.f);
                *(__half2*)&H3[(mr + g) * LDH3 + nl]     = __floats2half2_rn(f0, f1);
                *(__half2*)&H3[(mr + g + 8) * LDH3 + nl] = __floats2half2_rn(f2, f3);
            }
        }
        __syncthreads();

        // partial head dots over this CTA's 128 features; 2 points per thread
        const int pj = tid & 3, pp = tid >> 2;
        float* part = (float*)outp;
#pragma unroll
        for (int pass = 0; pass < 2; pass++) {
            int p = pp + pass * 64;
            const uint4* hr4 = (const uint4*)(H3 + p * LDH3);  // 16 x (8 halves)
            float v = 0.f;
#pragma unroll
            for (int k4 = 0; k4 < 16; k4++) {
                uint4 hv = hr4[k4];
                const __half2* hp = (const __half2*)&hv;
#pragma unroll
                for (int i = 0; i < 4; i++) {
                    float2 h = __half22float2(hp[i]);
                    float2 w = __half22float2(Whh[(k4 * 4 + i) * 4 + pj]);
                    v += h.x * w.x + h.y * w.y;
                }
            }
            part[(size_t)(nh * 4 + pj) * NPTS + (size_t)t * 128 + p] = v;
        }
        __syncthreads();  // head reads done before next tile's H3 staging
    }
}

// ============================================================================
// Final: combine partial head sums, apply bias + sigmoid / softplus.
// ============================================================================
__global__ void k_final(const float* __restrict__ part,
                        const float* __restrict__ bsig, const float* __restrict__ brgb,
                        float* __restrict__ out) {
    int i = blockIdx.x * blockDim.x + threadIdx.x;
    if (i >= 4 * NPTS) return;
    int j = i >> 20;
    int p = i & (NPTS - 1);
    float v = part[(size_t)j * NPTS + p] + part[(size_t)(4 + j) * NPTS + p];
    if (j < 3) {
        v += brgb[j];
        out[(size_t)p * 3 + j] = 1.f / (1.f + expf(-v));
    } else {
        v += bsig[0];
        out[(size_t)3 * NPTS + p] = (v > 20.f) ? v : log1pf(expf(v));
    }
}

// ============================================================================
extern "C" void kernel_launch(void* const* d_in, const int* in_sizes, int n_in,
                              void* d_out, int out_size) {
    const float* x    = (const float*)d_in[0];
    const float* fxy  = (const float*)d_in[1];
    const float* fxz  = (const float*)d_in[2];
    const float* fyz  = (const float*)d_in[3];
    const float* W0   = (const float*)d_in[4];
    const float* b0   = (const float*)d_in[5];
    const float* W1   = (const float*)d_in[6];
    const float* b1   = (const float*)d_in[7];
    const float* W2   = (const float*)d_in[8];
    const float* b2   = (const float*)d_in[9];
    const float* W3   = (const float*)d_in[10];
    const float* b3   = (const float*)d_in[11];
    const float* Wsig = (const float*)d_in[12];
    const float* bsig = (const float*)d_in[13];
    const float* Wrgb = (const float*)d_in[14];
    const float* brgb = (const float*)d_in[15];

    void *p1, *p2, *pf;
    cudaGetSymbolAddress(&p1, g_h1);
    cudaGetSymbolAddress(&p2, g_h2);
    cudaGetSymbolAddress(&pf, g_fp);

    int nsm = 148;
    cudaDeviceGetAttribute(&nsm, cudaDevAttrMultiProcessorCount, 0);
    int grid = nsm & ~1;  // even: parity split across n-halves

    const size_t S0 = 256 * LDW0 * 2 + 256 * 4 + 64 * LDW0 * 2;

    cudaFuncSetAttribute(k_enc0,       cudaFuncAttributeMaxDynamicSharedMemorySize, (int)S0);
    cudaFuncSetAttribute(k_regB16,     cudaFuncAttributeMaxDynamicSharedMemorySize, SMR_TOT_PLAIN);
    cudaFuncSetAttribute(k_regB_heads, cudaFuncAttributeMaxDynamicSharedMemorySize, SMR_TOT_HEADS);

    // pack tri-planes -> g_fp (pixel-major half8)
    k_pack<<<(3 * RES * RES + 255) / 256, 256>>>(fxy, fxz, fyz, (__half*)pf);
    // encode + L0 -> h1 (p1); 2 CTAs/SM
    k_enc0<<<2 * nsm, 256, S0>>>(x, (const __half*)pf, W0, b0, (__half*)p1);
    // L1: p1 -> p2 (fp16 accum)
    k_regB16<<<grid, 256, SMR_TOT_PLAIN>>>(W1, b1, (const __half*)p1, (__half*)p2);
    // L2: p2 -> p1 (fp16 accum)
    k_regB16<<<grid, 256, SMR_TOT_PLAIN>>>(W2, b2, (const __half*)p2, (__half*)p1);
    // L3 + partial heads (fp32 accum): p1 -> partial sums in p2
    k_regB_heads<<<grid, 256, SMR_TOT_HEADS>>>(W3, b3, Wsig, Wrgb,
                                               (const __half*)p1, p2);
    // combine partials -> out
    k_final<<<(4 * NPTS + 255) / 256, 256>>>((const float*)p2, bsig, brgb, (float*)d_out);
}